// round 14
// baseline (speedup 1.0000x reference)
#include <cuda_runtime.h>
#include <math.h>

#define Vocab 100000
#define Dim   256
#define Bb    32
#define Nn    128
#define Kk    100
#define NTOK  (Bb * Nn)            // 4096 tokens
#define ROWS  (Kk + 1)             // 101 gathered rows per token
#define NORM_TERM 11.512925f
#define LOG_K     4.6051702f       // log(100)
#define INV_NTOK  (1.0f / 4096.0f)

__device__ __forceinline__ float fast_softplus(float x) {
    float e = __expf(-fabsf(x));
    float l = __logf(1.0f + e);
    return (x > 0.0f) ? x + l : l;
}

// 256-bit weight-table load with L2 evict_last (the only load form that
// accepts an L2 policy hint on this ptxas: .v4.b64). Pins table lines in L2
// across graph replays.
union W256 { ulonglong4 u; float f[8]; };

__device__ __forceinline__ W256 ldg_evict_last_256(const void* p) {
    W256 v;
    asm volatile("ld.global.L2::evict_last.v4.b64 {%0,%1,%2,%3}, [%4];"
                 : "=l"(v.u.x), "=l"(v.u.y), "=l"(v.u.z), "=l"(v.u.w)
                 : "l"(p));
    return v;
}

__global__ void zero_out_kernel(float* out) {
    out[0] = 0.0f;
}

__global__ __launch_bounds__(256, 6)
void nce_loss_kernel(const int* __restrict__ target,        // (B,N)
                     const int* __restrict__ noise,         // (B,N,K)
                     const float* __restrict__ hidden,      // (B,N,D)
                     const float* __restrict__ weight,      // (V,D)
                     const float* __restrict__ bias,        // (V,)
                     const float* __restrict__ noise_probs, // (V,)
                     float* __restrict__ out)
{
    const int token = blockIdx.x;
    const int tid   = threadIdx.x;
    const int lane  = tid & 31;
    const int warp  = tid >> 5;            // 0..7
    const int g     = lane >> 3;           // row-group in warp: 0..3
    const int p     = lane & 7;            // position in 8-lane group

    __shared__ float hsh[Dim];
    __shared__ int   idsh[ROWS + 3];       // padded
    __shared__ float wsum[8];

    hsh[tid] = hidden[(size_t)token * Dim + tid];
    if (tid < ROWS)
        idsh[tid] = (tid == 0) ? target[token]
                               : noise[(size_t)token * Kk + (tid - 1)];
    __syncthreads();

    // 4 row streams per thread: r = warp*4 + g + 32*i
    const int r0 = warp * 4 + g;
    int  id[4];
    bool act[4];
    const char* wptr[4];
    #pragma unroll
    for (int i = 0; i < 4; i++) {
        const int r = r0 + 32 * i;
        act[i]  = (r < ROWS);
        id[i]   = act[i] ? idsh[r] : 0;
        wptr[i] = reinterpret_cast<const char*>(weight)
                + (size_t)id[i] * (Dim * 4) + p * 32;
    }

    float s[4] = {0.f, 0.f, 0.f, 0.f};

    // Row = 32 x 32B chunks; lane p handles chunks p+8j (j=0..3).
    // Per j, the 8-lane group covers a contiguous 256B span.
    #pragma unroll
    for (int j = 0; j < 4; j++) {
        const float4* hp =
            reinterpret_cast<const float4*>(hsh + 8 * (p + 8 * j));
        const float4 ha = hp[0];
        const float4 hb = hp[1];
        #pragma unroll
        for (int i = 0; i < 4; i++) {
            if (act[i]) {
                const W256 w = ldg_evict_last_256(wptr[i] + j * 256);
                s[i] += ha.x * w.f[0] + ha.y * w.f[1]
                      + ha.z * w.f[2] + ha.w * w.f[3]
                      + hb.x * w.f[4] + hb.y * w.f[5]
                      + hb.z * w.f[6] + hb.w * w.f[7];
            }
        }
    }

    // reduce each stream across its 8-lane group
    #pragma unroll
    for (int i = 0; i < 4; i++) {
        s[i] += __shfl_xor_sync(0xFFFFFFFFu, s[i], 1);
        s[i] += __shfl_xor_sync(0xFFFFFFFFu, s[i], 2);
        s[i] += __shfl_xor_sync(0xFFFFFFFFu, s[i], 4);
    }

    float local = 0.0f;
    if (p == 0) {
        #pragma unroll
        for (int i = 0; i < 4; i++) {
            if (act[i]) {
                const int r = r0 + 32 * i;
                const float score = s[i] + bias[id[i]] - NORM_TERM;
                if (r == 0) {
                    local += fast_softplus(-(score - LOG_K));
                } else {
                    const float sn = __logf(noise_probs[id[i]]);
                    local += fast_softplus(score - sn - LOG_K);
                }
            }
        }
    }

    // warp reduce (nonzero only on lanes 0,8,16,24)
    #pragma unroll
    for (int o = 16; o > 0; o >>= 1)
        local += __shfl_xor_sync(0xFFFFFFFFu, local, o);

    if (lane == 0) wsum[warp] = local;
    __syncthreads();
    if (tid == 0) {
        float t = 0.0f;
        #pragma unroll
        for (int i = 0; i < 8; i++) t += wsum[i];
        atomicAdd(out, t * INV_NTOK);
    }
}

extern "C" void kernel_launch(void* const* d_in, const int* in_sizes, int n_in,
                              void* d_out, int out_size)
{
    const int*   target      = (const int*)  d_in[0];
    const int*   noise       = (const int*)  d_in[1];
    const float* hidden      = (const float*)d_in[2];
    const float* weight      = (const float*)d_in[3];
    const float* bias        = (const float*)d_in[4];
    const float* noise_probs = (const float*)d_in[5];
    float* out = (float*)d_out;

    zero_out_kernel<<<1, 1>>>(out);
    nce_loss_kernel<<<NTOK, 256>>>(target, noise, hidden, weight, bias,
                                   noise_probs, out);
}